// round 1
// baseline (speedup 1.0000x reference)
#include <cuda_runtime.h>
#include <math.h>

#define N_ENT 100000
#define DIM   128
#define NB    50000
#define NR    8
#define NE    200000

// Scratch (device globals: allowed, no runtime allocation)
__device__ float g_Te[(size_t)N_ENT * DIM];  // transformed embeddings for current relation
__device__ float g_Z [(size_t)N_ENT * DIM];  // per-node output-space accumulator

// ---------------------------------------------------------------------------
// Zero Z
// ---------------------------------------------------------------------------
__global__ void __launch_bounds__(256) zero_Z_k() {
    const int n4 = N_ENT * DIM / 4;
    float4 z = make_float4(0.f, 0.f, 0.f, 0.f);
    for (int i = blockIdx.x * blockDim.x + threadIdx.x; i < n4;
         i += gridDim.x * blockDim.x) {
        reinterpret_cast<float4*>(g_Z)[i] = z;
    }
}

// ---------------------------------------------------------------------------
// Te = A[M,128] @ W[128,128]  (fp32, BM=64, BN=128, BK=32, 8x4 microtile)
// ---------------------------------------------------------------------------
__global__ void __launch_bounds__(256) gemm_te(const float* __restrict__ A,
                                               const float* __restrict__ W,
                                               int M) {
    __shared__ float As[32][64];    // [k][m]
    __shared__ float Ws[32][128];   // [k][n]
    const int tid = threadIdx.x;
    const int tx  = tid & 31;       // cols tx*4 .. tx*4+3
    const int ty  = tid >> 5;       // rows ty*8 .. ty*8+7
    const int m0  = blockIdx.x * 64;

    float acc[8][4];
#pragma unroll
    for (int i = 0; i < 8; i++)
#pragma unroll
        for (int j = 0; j < 4; j++) acc[i][j] = 0.f;

    for (int k0 = 0; k0 < 128; k0 += 32) {
        // load A tile (64 rows x 32 k), store transposed
#pragma unroll
        for (int i = 0; i < 2; i++) {
            int li  = tid + i * 256;      // 0..511
            int row = li >> 3;            // 0..63
            int c4  = li & 7;             // float4 within 32 k
            float4 v = make_float4(0.f, 0.f, 0.f, 0.f);
            int gr = m0 + row;
            if (gr < M)
                v = *reinterpret_cast<const float4*>(&A[(size_t)gr * 128 + k0 + c4 * 4]);
            As[c4 * 4 + 0][row] = v.x;
            As[c4 * 4 + 1][row] = v.y;
            As[c4 * 4 + 2][row] = v.z;
            As[c4 * 4 + 3][row] = v.w;
        }
        // load W tile (32 k x 128 n)
#pragma unroll
        for (int i = 0; i < 4; i++) {
            int li = tid + i * 256;       // 0..1023
            int kk = li >> 5;             // 0..31
            int c4 = li & 31;             // 0..31
            *reinterpret_cast<float4*>(&Ws[kk][c4 * 4]) =
                *reinterpret_cast<const float4*>(&W[(size_t)(k0 + kk) * 128 + c4 * 4]);
        }
        __syncthreads();

#pragma unroll
        for (int k = 0; k < 32; k++) {
            float4 b  = *reinterpret_cast<float4*>(&Ws[k][tx * 4]);
            float4 a0 = *reinterpret_cast<float4*>(&As[k][ty * 8]);
            float4 a1 = *reinterpret_cast<float4*>(&As[k][ty * 8 + 4]);
            float a[8] = {a0.x, a0.y, a0.z, a0.w, a1.x, a1.y, a1.z, a1.w};
#pragma unroll
            for (int i = 0; i < 8; i++) {
                acc[i][0] += a[i] * b.x;
                acc[i][1] += a[i] * b.y;
                acc[i][2] += a[i] * b.z;
                acc[i][3] += a[i] * b.w;
            }
        }
        __syncthreads();
    }

#pragma unroll
    for (int i = 0; i < 8; i++) {
        int gr = m0 + ty * 8 + i;
        if (gr < M) {
            float4 v = make_float4(acc[i][0], acc[i][1], acc[i][2], acc[i][3]);
            *reinterpret_cast<float4*>(&g_Te[(size_t)gr * 128 + tx * 4]) = v;
        }
    }
}

// ---------------------------------------------------------------------------
// Scatter: Z[src] += val * Te[dst]   (one edge per warp, red.v4 per lane)
// ---------------------------------------------------------------------------
__global__ void __launch_bounds__(256) scatter_k(const int*   __restrict__ src,
                                                 const int*   __restrict__ dst,
                                                 const float* __restrict__ val) {
    int w    = (blockIdx.x * 256 + threadIdx.x) >> 5;
    int lane = threadIdx.x & 31;
    if (w >= NE) return;
    int   s = __ldg(&src[w]);
    int   d = __ldg(&dst[w]);
    float v = __ldg(&val[w]);
    float4 t = *reinterpret_cast<const float4*>(&g_Te[(size_t)d * 128 + lane * 4]);
    float* zp = &g_Z[(size_t)s * 128 + lane * 4];
    asm volatile("red.global.add.v4.f32 [%0], {%1, %2, %3, %4};"
                 :: "l"(zp), "f"(t.x * v), "f"(t.y * v), "f"(t.z * v), "f"(t.w * v)
                 : "memory");
}

// ---------------------------------------------------------------------------
// out = sigmoid(X @ S + Z[idx])     (same GEMM skeleton + gather epilogue)
// ---------------------------------------------------------------------------
__global__ void __launch_bounds__(256) out_kernel(const float* __restrict__ X,
                                                  const float* __restrict__ S,
                                                  const int*   __restrict__ idx,
                                                  float*       __restrict__ out,
                                                  int M) {
    __shared__ float As[32][64];
    __shared__ float Ws[32][128];
    const int tid = threadIdx.x;
    const int tx  = tid & 31;
    const int ty  = tid >> 5;
    const int m0  = blockIdx.x * 64;

    float acc[8][4];
#pragma unroll
    for (int i = 0; i < 8; i++)
#pragma unroll
        for (int j = 0; j < 4; j++) acc[i][j] = 0.f;

    for (int k0 = 0; k0 < 128; k0 += 32) {
#pragma unroll
        for (int i = 0; i < 2; i++) {
            int li  = tid + i * 256;
            int row = li >> 3;
            int c4  = li & 7;
            float4 v = make_float4(0.f, 0.f, 0.f, 0.f);
            int gr = m0 + row;
            if (gr < M)
                v = *reinterpret_cast<const float4*>(&X[(size_t)gr * 128 + k0 + c4 * 4]);
            As[c4 * 4 + 0][row] = v.x;
            As[c4 * 4 + 1][row] = v.y;
            As[c4 * 4 + 2][row] = v.z;
            As[c4 * 4 + 3][row] = v.w;
        }
#pragma unroll
        for (int i = 0; i < 4; i++) {
            int li = tid + i * 256;
            int kk = li >> 5;
            int c4 = li & 31;
            *reinterpret_cast<float4*>(&Ws[kk][c4 * 4]) =
                *reinterpret_cast<const float4*>(&S[(size_t)(k0 + kk) * 128 + c4 * 4]);
        }
        __syncthreads();

#pragma unroll
        for (int k = 0; k < 32; k++) {
            float4 b  = *reinterpret_cast<float4*>(&Ws[k][tx * 4]);
            float4 a0 = *reinterpret_cast<float4*>(&As[k][ty * 8]);
            float4 a1 = *reinterpret_cast<float4*>(&As[k][ty * 8 + 4]);
            float a[8] = {a0.x, a0.y, a0.z, a0.w, a1.x, a1.y, a1.z, a1.w};
#pragma unroll
            for (int i = 0; i < 8; i++) {
                acc[i][0] += a[i] * b.x;
                acc[i][1] += a[i] * b.y;
                acc[i][2] += a[i] * b.z;
                acc[i][3] += a[i] * b.w;
            }
        }
        __syncthreads();
    }

#pragma unroll
    for (int i = 0; i < 8; i++) {
        int gr = m0 + ty * 8 + i;
        if (gr < M) {
            int node = __ldg(&idx[gr]);
            float4 z = *reinterpret_cast<const float4*>(&g_Z[(size_t)node * 128 + tx * 4]);
            float4 o;
            o.x = 1.f / (1.f + expf(-(acc[i][0] + z.x)));
            o.y = 1.f / (1.f + expf(-(acc[i][1] + z.y)));
            o.z = 1.f / (1.f + expf(-(acc[i][2] + z.z)));
            o.w = 1.f / (1.f + expf(-(acc[i][3] + z.w)));
            *reinterpret_cast<float4*>(&out[(size_t)gr * 128 + tx * 4]) = o;
        }
    }
}

// ---------------------------------------------------------------------------
// Launch
// ---------------------------------------------------------------------------
extern "C" void kernel_launch(void* const* d_in, const int* in_sizes, int n_in,
                              void* d_out, int out_size) {
    const float* emb      = (const float*)d_in[0];
    const float* head_e   = (const float*)d_in[1];
    const float* tail_e   = (const float*)d_in[2];
    const float* relk     = (const float*)d_in[3];  // [R,128,128]
    const float* selfk    = (const float*)d_in[4];  // [128,128]
    const float* edge_val = (const float*)d_in[5];  // [R,E]
    const int*   head_idx = (const int*)d_in[6];
    const int*   tail_idx = (const int*)d_in[7];
    const int*   edge_src = (const int*)d_in[8];    // [R,E]
    const int*   edge_dst = (const int*)d_in[9];    // [R,E]
    float*       out      = (float*)d_out;          // [2, B, 128], head first

    zero_Z_k<<<2048, 256>>>();

    const int gemm_blocks = (N_ENT + 63) / 64;        // 1563
    const int scat_blocks = (NE * 32 + 255) / 256;    // 25000
    for (int r = 0; r < NR; r++) {
        gemm_te<<<gemm_blocks, 256>>>(emb, relk + (size_t)r * 128 * 128, N_ENT);
        scatter_k<<<scat_blocks, 256>>>(edge_src + (size_t)r * NE,
                                        edge_dst + (size_t)r * NE,
                                        edge_val + (size_t)r * NE);
    }

    const int out_blocks = (NB + 63) / 64;            // 782
    out_kernel<<<out_blocks, 256>>>(head_e, selfk, head_idx, out, NB);
    out_kernel<<<out_blocks, 256>>>(tail_e, selfk, tail_idx,
                                    out + (size_t)NB * 128, NB);
}

// round 2
// speedup vs baseline: 1.0925x; 1.0925x over previous
#include <cuda_runtime.h>
#include <math.h>

#define N_ENT 100000
#define DIM   128
#define NB    50000
#define NR    8
#define NE    200000

__device__ float g_Te[(size_t)N_ENT * DIM];  // transformed embeddings, current relation
__device__ float g_Z [(size_t)N_ENT * DIM];  // per-node output-space accumulator

// ---------------------------------------------------------------------------
// helpers: tf32 split + mma
// ---------------------------------------------------------------------------
__device__ __forceinline__ unsigned f2tf32(float x) {
    unsigned r;
    asm("cvt.rna.tf32.f32 %0, %1;" : "=r"(r) : "f"(x));
    return r;
}
__device__ __forceinline__ void split_tf32(float x, unsigned& hi, unsigned& lo) {
    hi = f2tf32(x);
    lo = f2tf32(x - __uint_as_float(hi));
}
__device__ __forceinline__ void mma_tf32(float* c, const unsigned* a, const unsigned* b) {
    asm volatile(
        "mma.sync.aligned.m16n8k8.row.col.f32.tf32.tf32.f32 "
        "{%0,%1,%2,%3}, {%4,%5,%6,%7}, {%8,%9}, {%0,%1,%2,%3};"
        : "+f"(c[0]), "+f"(c[1]), "+f"(c[2]), "+f"(c[3])
        : "r"(a[0]), "r"(a[1]), "r"(a[2]), "r"(a[3]), "r"(b[0]), "r"(b[1]));
}

// ---------------------------------------------------------------------------
// Zero Z
// ---------------------------------------------------------------------------
__global__ void __launch_bounds__(256) zero_Z_k() {
    const int n4 = N_ENT * DIM / 4;
    float4 z = make_float4(0.f, 0.f, 0.f, 0.f);
    for (int i = blockIdx.x * blockDim.x + threadIdx.x; i < n4;
         i += gridDim.x * blockDim.x) {
        reinterpret_cast<float4*>(g_Z)[i] = z;
    }
}

// ---------------------------------------------------------------------------
// Shared GEMM core: C_tile = A[128 rows, 128] @ W[128,128] via 3xTF32 mma.
// EPI=0: write to g_Te.  EPI=1: out = sigmoid(acc + Z[idx[row]]).
// Block 256 thr = 8 warps (4 m x 2 n), warp tile 32x64, BK=32.
// ---------------------------------------------------------------------------
template <int EPI>
__device__ __forceinline__ void gemm_core(const float* __restrict__ A,
                                          const float* __restrict__ W,
                                          const int*   __restrict__ idx,
                                          float*       __restrict__ out,
                                          int M) {
    __shared__ float As[128][36];   // [m][k], pad-> conflict-free frag loads
    __shared__ float Ws[32][136];   // [k][n]

    const int tid    = threadIdx.x;
    const int lane   = tid & 31;
    const int wid    = tid >> 5;
    const int warp_m = wid >> 1;          // 0..3  -> rows warp_m*32
    const int warp_n = wid & 1;           // 0..1  -> cols warp_n*64
    const int m0     = blockIdx.x * 128;
    const int gq     = lane >> 2;         // groupID
    const int tg     = lane & 3;          // thread-in-group

    float acc[2][8][4];
#pragma unroll
    for (int i = 0; i < 2; i++)
#pragma unroll
        for (int j = 0; j < 8; j++)
#pragma unroll
            for (int k = 0; k < 4; k++) acc[i][j][k] = 0.f;

    for (int k0 = 0; k0 < 128; k0 += 32) {
        // load A tile: 128 rows x 32 k
#pragma unroll
        for (int i = 0; i < 4; i++) {
            int li  = tid + i * 256;      // 0..1023
            int row = li >> 3;            // 0..127
            int c4  = li & 7;             // float4 within 32 k
            float4 v = make_float4(0.f, 0.f, 0.f, 0.f);
            int gr = m0 + row;
            if (gr < M)
                v = *reinterpret_cast<const float4*>(&A[(size_t)gr * 128 + k0 + c4 * 4]);
            As[row][c4 * 4 + 0] = v.x;
            As[row][c4 * 4 + 1] = v.y;
            As[row][c4 * 4 + 2] = v.z;
            As[row][c4 * 4 + 3] = v.w;
        }
        // load W tile: 32 k x 128 n
#pragma unroll
        for (int i = 0; i < 4; i++) {
            int li = tid + i * 256;
            int kk = li >> 5;             // 0..31
            int c4 = li & 31;
            float4 v = *reinterpret_cast<const float4*>(&W[(size_t)(k0 + kk) * 128 + c4 * 4]);
            Ws[kk][c4 * 4 + 0] = v.x;
            Ws[kk][c4 * 4 + 1] = v.y;
            Ws[kk][c4 * 4 + 2] = v.z;
            Ws[kk][c4 * 4 + 3] = v.w;
        }
        __syncthreads();

#pragma unroll
        for (int ks = 0; ks < 4; ks++) {  // four k8 steps
            // A fragments (2 m-tiles), hi/lo split
            unsigned ahi[2][4], alo[2][4];
#pragma unroll
            for (int mt = 0; mt < 2; mt++) {
                int r0 = warp_m * 32 + mt * 16 + gq;
                int c0 = ks * 8 + tg;
                split_tf32(As[r0    ][c0    ], ahi[mt][0], alo[mt][0]);
                split_tf32(As[r0 + 8][c0    ], ahi[mt][1], alo[mt][1]);
                split_tf32(As[r0    ][c0 + 4], ahi[mt][2], alo[mt][2]);
                split_tf32(As[r0 + 8][c0 + 4], ahi[mt][3], alo[mt][3]);
            }
#pragma unroll
            for (int nt = 0; nt < 8; nt++) {
                int cn = warp_n * 64 + nt * 8 + gq;
                unsigned bhi[2], blo[2];
                split_tf32(Ws[ks * 8 + tg    ][cn], bhi[0], blo[0]);
                split_tf32(Ws[ks * 8 + tg + 4][cn], bhi[1], blo[1]);
#pragma unroll
                for (int mt = 0; mt < 2; mt++) {
                    mma_tf32(acc[mt][nt], ahi[mt], bhi);
                    mma_tf32(acc[mt][nt], alo[mt], bhi);
                    mma_tf32(acc[mt][nt], ahi[mt], blo);
                }
            }
        }
        __syncthreads();
    }

    // epilogue: C layout c0,c1 @ (row=gq, col=2*tg, +1); c2,c3 @ row=gq+8
#pragma unroll
    for (int mt = 0; mt < 2; mt++) {
#pragma unroll
        for (int half = 0; half < 2; half++) {
            int gr = m0 + warp_m * 32 + mt * 16 + gq + half * 8;
            if (gr >= M) continue;
            if (EPI == 0) {
#pragma unroll
                for (int nt = 0; nt < 8; nt++) {
                    int col = warp_n * 64 + nt * 8 + 2 * tg;
                    float2 v = make_float2(acc[mt][nt][half * 2 + 0],
                                           acc[mt][nt][half * 2 + 1]);
                    *reinterpret_cast<float2*>(&g_Te[(size_t)gr * 128 + col]) = v;
                }
            } else {
                int node = __ldg(&idx[gr]);
#pragma unroll
                for (int nt = 0; nt < 8; nt++) {
                    int col = warp_n * 64 + nt * 8 + 2 * tg;
                    float2 z = *reinterpret_cast<const float2*>(&g_Z[(size_t)node * 128 + col]);
                    float2 o;
                    o.x = 1.f / (1.f + expf(-(acc[mt][nt][half * 2 + 0] + z.x)));
                    o.y = 1.f / (1.f + expf(-(acc[mt][nt][half * 2 + 1] + z.y)));
                    *reinterpret_cast<float2*>(&out[(size_t)gr * 128 + col]) = o;
                }
            }
        }
    }
}

__global__ void __launch_bounds__(256) gemm_te_tc(const float* __restrict__ A,
                                                  const float* __restrict__ W,
                                                  int M) {
    gemm_core<0>(A, W, nullptr, nullptr, M);
}

__global__ void __launch_bounds__(256) out_tc(const float* __restrict__ X,
                                              const float* __restrict__ S,
                                              const int*   __restrict__ idx,
                                              float*       __restrict__ out,
                                              int M) {
    gemm_core<1>(X, S, idx, out, M);
}

// ---------------------------------------------------------------------------
// Scatter: Z[src] += val * Te[dst]   (one edge per warp, red.v4 per lane)
// ---------------------------------------------------------------------------
__global__ void __launch_bounds__(256) scatter_k(const int*   __restrict__ src,
                                                 const int*   __restrict__ dst,
                                                 const float* __restrict__ val) {
    int w    = (blockIdx.x * 256 + threadIdx.x) >> 5;
    int lane = threadIdx.x & 31;
    if (w >= NE) return;
    int   s = __ldg(&src[w]);
    int   d = __ldg(&dst[w]);
    float v = __ldg(&val[w]);
    float4 t = *reinterpret_cast<const float4*>(&g_Te[(size_t)d * 128 + lane * 4]);
    float* zp = &g_Z[(size_t)s * 128 + lane * 4];
    asm volatile("red.global.add.v4.f32 [%0], {%1, %2, %3, %4};"
                 :: "l"(zp), "f"(t.x * v), "f"(t.y * v), "f"(t.z * v), "f"(t.w * v)
                 : "memory");
}

// ---------------------------------------------------------------------------
// Launch
// ---------------------------------------------------------------------------
extern "C" void kernel_launch(void* const* d_in, const int* in_sizes, int n_in,
                              void* d_out, int out_size) {
    const float* emb      = (const float*)d_in[0];
    const float* head_e   = (const float*)d_in[1];
    const float* tail_e   = (const float*)d_in[2];
    const float* relk     = (const float*)d_in[3];  // [R,128,128]
    const float* selfk    = (const float*)d_in[4];  // [128,128]
    const float* edge_val = (const float*)d_in[5];  // [R,E]
    const int*   head_idx = (const int*)d_in[6];
    const int*   tail_idx = (const int*)d_in[7];
    const int*   edge_src = (const int*)d_in[8];    // [R,E]
    const int*   edge_dst = (const int*)d_in[9];    // [R,E]
    float*       out      = (float*)d_out;          // [2, B, 128], head first

    zero_Z_k<<<2048, 256>>>();

    const int gemm_blocks = (N_ENT + 127) / 128;      // 782
    const int scat_blocks = (NE * 32 + 255) / 256;    // 25000
    for (int r = 0; r < NR; r++) {
        gemm_te_tc<<<gemm_blocks, 256>>>(emb, relk + (size_t)r * 128 * 128, N_ENT);
        scatter_k<<<scat_blocks, 256>>>(edge_src + (size_t)r * NE,
                                        edge_dst + (size_t)r * NE,
                                        edge_val + (size_t)r * NE);
    }

    const int out_blocks = (NB + 127) / 128;          // 391
    out_tc<<<out_blocks, 256>>>(head_e, selfk, head_idx, out, NB);
    out_tc<<<out_blocks, 256>>>(tail_e, selfk, tail_idx,
                                out + (size_t)NB * 128, NB);
}

// round 3
// speedup vs baseline: 1.1873x; 1.0868x over previous
#include <cuda_runtime.h>
#include <math.h>

#define N_ENT 100000
#define DIM   128
#define NB    50000
#define NR    8
#define NE    200000

__device__ float g_Te[(size_t)N_ENT * DIM];  // transformed embeddings, current relation
__device__ float g_Z [(size_t)N_ENT * DIM];  // per-node output-space accumulator

// dynamic smem layout (floats):
//   As_hi[64][36]   @ 0        (2304)
//   As_lo[64][36]   @ 2304
//   Ws_hi[32][136]  @ 4608     (4352)
//   Ws_lo[32][136]  @ 8960
#define SM_AS_LO 2304
#define SM_WS_HI 4608
#define SM_WS_LO 8960
#define SMEM_FLOATS 13312
#define SMEM_BYTES  (SMEM_FLOATS * 4)

// ---------------------------------------------------------------------------
// helpers: tf32 split + mma
// ---------------------------------------------------------------------------
__device__ __forceinline__ unsigned f2tf32(float x) {
    unsigned r;
    asm("cvt.rna.tf32.f32 %0, %1;" : "=r"(r) : "f"(x));
    return r;
}
__device__ __forceinline__ void split_tf32(float x, float& hi, float& lo) {
    unsigned h = f2tf32(x);
    hi = __uint_as_float(h);
    lo = __uint_as_float(f2tf32(x - hi));
}
__device__ __forceinline__ void mma_tf32(float* c, const unsigned* a, const unsigned* b) {
    asm volatile(
        "mma.sync.aligned.m16n8k8.row.col.f32.tf32.tf32.f32 "
        "{%0,%1,%2,%3}, {%4,%5,%6,%7}, {%8,%9}, {%0,%1,%2,%3};"
        : "+f"(c[0]), "+f"(c[1]), "+f"(c[2]), "+f"(c[3])
        : "r"(a[0]), "r"(a[1]), "r"(a[2]), "r"(a[3]), "r"(b[0]), "r"(b[1]));
}

// ---------------------------------------------------------------------------
// Zero Z
// ---------------------------------------------------------------------------
__global__ void __launch_bounds__(256) zero_Z_k() {
    const int n4 = N_ENT * DIM / 4;
    float4 z = make_float4(0.f, 0.f, 0.f, 0.f);
    for (int i = blockIdx.x * blockDim.x + threadIdx.x; i < n4;
         i += gridDim.x * blockDim.x) {
        reinterpret_cast<float4*>(g_Z)[i] = z;
    }
}

// ---------------------------------------------------------------------------
// GEMM core: C[64 rows, 128] = A @ W via 3xTF32, pre-split hi/lo in smem.
// 256 thr = 8 warps (2 m x 4 n), warp tile 32x32, BK=32.
// EPI=0: C -> g_Te.   EPI=1: out = sigmoid(C + Z[idx[row]]).
// ---------------------------------------------------------------------------
template <int EPI>
__device__ __forceinline__ void gemm_core(const float* __restrict__ A,
                                          const float* __restrict__ W,
                                          const int*   __restrict__ idx,
                                          float*       __restrict__ out,
                                          int M) {
    extern __shared__ float sm[];
    float* As_hi = sm;
    float* As_lo = sm + SM_AS_LO;
    float* Ws_hi = sm + SM_WS_HI;
    float* Ws_lo = sm + SM_WS_LO;

    const int tid    = threadIdx.x;
    const int lane   = tid & 31;
    const int wid    = tid >> 5;
    const int warp_m = wid >> 2;          // 0..1 -> rows warp_m*32
    const int warp_n = wid & 3;           // 0..3 -> cols warp_n*32
    const int m0     = blockIdx.x * 64;
    const int gq     = lane >> 2;         // 0..7
    const int tg     = lane & 3;          // 0..3

    float acc[2][4][4];
#pragma unroll
    for (int i = 0; i < 2; i++)
#pragma unroll
        for (int j = 0; j < 4; j++)
#pragma unroll
            for (int k = 0; k < 4; k++) acc[i][j][k] = 0.f;

#pragma unroll
    for (int k0 = 0; k0 < 128; k0 += 32) {
        // ---- load + pre-split A tile: 64 rows x 32 k ----
#pragma unroll
        for (int i = 0; i < 2; i++) {
            int li  = tid + i * 256;          // 0..511
            int row = li >> 3;                // 0..63
            int c4  = li & 7;
            float4 v = make_float4(0.f, 0.f, 0.f, 0.f);
            int gr = m0 + row;
            if (gr < M)
                v = *reinterpret_cast<const float4*>(&A[(size_t)gr * 128 + k0 + c4 * 4]);
            float h, l;
            int base = row * 36 + c4 * 4;
            split_tf32(v.x, h, l); As_hi[base + 0] = h; As_lo[base + 0] = l;
            split_tf32(v.y, h, l); As_hi[base + 1] = h; As_lo[base + 1] = l;
            split_tf32(v.z, h, l); As_hi[base + 2] = h; As_lo[base + 2] = l;
            split_tf32(v.w, h, l); As_hi[base + 3] = h; As_lo[base + 3] = l;
        }
        // ---- load + pre-split W tile: 32 k x 128 n ----
#pragma unroll
        for (int i = 0; i < 4; i++) {
            int li = tid + i * 256;           // 0..1023
            int kk = li >> 5;                 // 0..31
            int c4 = li & 31;
            float4 v = *reinterpret_cast<const float4*>(&W[(size_t)(k0 + kk) * 128 + c4 * 4]);
            float h, l;
            int base = kk * 136 + c4 * 4;
            split_tf32(v.x, h, l); Ws_hi[base + 0] = h; Ws_lo[base + 0] = l;
            split_tf32(v.y, h, l); Ws_hi[base + 1] = h; Ws_lo[base + 1] = l;
            split_tf32(v.z, h, l); Ws_hi[base + 2] = h; Ws_lo[base + 2] = l;
            split_tf32(v.w, h, l); Ws_hi[base + 3] = h; Ws_lo[base + 3] = l;
        }
        __syncthreads();

#pragma unroll
        for (int ks = 0; ks < 4; ks++) {
            // A fragments, 2 m-tiles
            unsigned ahi[2][4], alo[2][4];
#pragma unroll
            for (int mt = 0; mt < 2; mt++) {
                int r0 = warp_m * 32 + mt * 16 + gq;
                int c0 = ks * 8 + tg;
                ahi[mt][0] = __float_as_uint(As_hi[(r0    ) * 36 + c0    ]);
                ahi[mt][1] = __float_as_uint(As_hi[(r0 + 8) * 36 + c0    ]);
                ahi[mt][2] = __float_as_uint(As_hi[(r0    ) * 36 + c0 + 4]);
                ahi[mt][3] = __float_as_uint(As_hi[(r0 + 8) * 36 + c0 + 4]);
                alo[mt][0] = __float_as_uint(As_lo[(r0    ) * 36 + c0    ]);
                alo[mt][1] = __float_as_uint(As_lo[(r0 + 8) * 36 + c0    ]);
                alo[mt][2] = __float_as_uint(As_lo[(r0    ) * 36 + c0 + 4]);
                alo[mt][3] = __float_as_uint(As_lo[(r0 + 8) * 36 + c0 + 4]);
            }
            // B fragments, 4 n-tiles
            unsigned bhi[4][2], blo[4][2];
#pragma unroll
            for (int nt = 0; nt < 4; nt++) {
                int cn = warp_n * 32 + nt * 8 + gq;
                int r  = ks * 8 + tg;
                bhi[nt][0] = __float_as_uint(Ws_hi[(r    ) * 136 + cn]);
                bhi[nt][1] = __float_as_uint(Ws_hi[(r + 4) * 136 + cn]);
                blo[nt][0] = __float_as_uint(Ws_lo[(r    ) * 136 + cn]);
                blo[nt][1] = __float_as_uint(Ws_lo[(r + 4) * 136 + cn]);
            }
#pragma unroll
            for (int nt = 0; nt < 4; nt++)
#pragma unroll
                for (int mt = 0; mt < 2; mt++) {
                    mma_tf32(acc[mt][nt], ahi[mt], bhi[nt]);
                    mma_tf32(acc[mt][nt], alo[mt], bhi[nt]);
                    mma_tf32(acc[mt][nt], ahi[mt], blo[nt]);
                }
        }
        __syncthreads();
    }

    // epilogue: c0,c1 @ (row gq, cols 2tg,2tg+1), c2,c3 @ row gq+8
#pragma unroll
    for (int mt = 0; mt < 2; mt++) {
#pragma unroll
        for (int half = 0; half < 2; half++) {
            int gr = m0 + warp_m * 32 + mt * 16 + gq + half * 8;
            if (gr >= M) continue;
            if (EPI == 0) {
#pragma unroll
                for (int nt = 0; nt < 4; nt++) {
                    int col = warp_n * 32 + nt * 8 + 2 * tg;
                    float2 v = make_float2(acc[mt][nt][half * 2 + 0],
                                           acc[mt][nt][half * 2 + 1]);
                    *reinterpret_cast<float2*>(&g_Te[(size_t)gr * 128 + col]) = v;
                }
            } else {
                int node = __ldg(&idx[gr]);
#pragma unroll
                for (int nt = 0; nt < 4; nt++) {
                    int col = warp_n * 32 + nt * 8 + 2 * tg;
                    float2 z = *reinterpret_cast<const float2*>(&g_Z[(size_t)node * 128 + col]);
                    float2 o;
                    o.x = 1.f / (1.f + expf(-(acc[mt][nt][half * 2 + 0] + z.x)));
                    o.y = 1.f / (1.f + expf(-(acc[mt][nt][half * 2 + 1] + z.y)));
                    *reinterpret_cast<float2*>(&out[(size_t)gr * 128 + col]) = o;
                }
            }
        }
    }
}

__global__ void __launch_bounds__(256, 3) gemm_te_tc(const float* __restrict__ A,
                                                     const float* __restrict__ W,
                                                     int M) {
    gemm_core<0>(A, W, nullptr, nullptr, M);
}

__global__ void __launch_bounds__(256, 3) out_tc(const float* __restrict__ X,
                                                 const float* __restrict__ S,
                                                 const int*   __restrict__ idx,
                                                 float*       __restrict__ out,
                                                 int M) {
    gemm_core<1>(X, S, idx, out, M);
}

// ---------------------------------------------------------------------------
// Scatter: Z[src] += val * Te[dst]   (one edge per warp, red.v4 per lane)
// ---------------------------------------------------------------------------
__global__ void __launch_bounds__(256) scatter_k(const int*   __restrict__ src,
                                                 const int*   __restrict__ dst,
                                                 const float* __restrict__ val) {
    int w    = (blockIdx.x * 256 + threadIdx.x) >> 5;
    int lane = threadIdx.x & 31;
    if (w >= NE) return;
    int   s = __ldg(&src[w]);
    int   d = __ldg(&dst[w]);
    float v = __ldg(&val[w]);
    float4 t = *reinterpret_cast<const float4*>(&g_Te[(size_t)d * 128 + lane * 4]);
    float* zp = &g_Z[(size_t)s * 128 + lane * 4];
    asm volatile("red.global.add.v4.f32 [%0], {%1, %2, %3, %4};"
                 :: "l"(zp), "f"(t.x * v), "f"(t.y * v), "f"(t.z * v), "f"(t.w * v)
                 : "memory");
}

// ---------------------------------------------------------------------------
// Launch
// ---------------------------------------------------------------------------
extern "C" void kernel_launch(void* const* d_in, const int* in_sizes, int n_in,
                              void* d_out, int out_size) {
    const float* emb      = (const float*)d_in[0];
    const float* head_e   = (const float*)d_in[1];
    const float* tail_e   = (const float*)d_in[2];
    const float* relk     = (const float*)d_in[3];  // [R,128,128]
    const float* selfk    = (const float*)d_in[4];  // [128,128]
    const float* edge_val = (const float*)d_in[5];  // [R,E]
    const int*   head_idx = (const int*)d_in[6];
    const int*   tail_idx = (const int*)d_in[7];
    const int*   edge_src = (const int*)d_in[8];    // [R,E]
    const int*   edge_dst = (const int*)d_in[9];    // [R,E]
    float*       out      = (float*)d_out;          // [2, B, 128], head first

    static bool attr_done = false;
    if (!attr_done) {
        cudaFuncSetAttribute(gemm_te_tc, cudaFuncAttributeMaxDynamicSharedMemorySize, SMEM_BYTES);
        cudaFuncSetAttribute(out_tc,     cudaFuncAttributeMaxDynamicSharedMemorySize, SMEM_BYTES);
        attr_done = true;
    }

    zero_Z_k<<<2048, 256>>>();

    const int gemm_blocks = (N_ENT + 63) / 64;        // 1563
    const int scat_blocks = (NE * 32 + 255) / 256;    // 25000
    for (int r = 0; r < NR; r++) {
        gemm_te_tc<<<gemm_blocks, 256, SMEM_BYTES>>>(emb, relk + (size_t)r * 128 * 128, N_ENT);
        scatter_k<<<scat_blocks, 256>>>(edge_src + (size_t)r * NE,
                                        edge_dst + (size_t)r * NE,
                                        edge_val + (size_t)r * NE);
    }

    const int out_blocks = (NB + 63) / 64;            // 782
    out_tc<<<out_blocks, 256, SMEM_BYTES>>>(head_e, selfk, head_idx, out, NB);
    out_tc<<<out_blocks, 256, SMEM_BYTES>>>(tail_e, selfk, tail_idx,
                                            out + (size_t)NB * 128, NB);
}

// round 6
// speedup vs baseline: 1.4366x; 1.2099x over previous
#include <cuda_runtime.h>
#include <cuda_bf16.h>
#include <math.h>

#define N_ENT 100000
#define DIM   128
#define NB    50000
#define NR    8
#define NE    200000

// ---------------------------------------------------------------------------
// Device scratch
// ---------------------------------------------------------------------------
__device__ float    g_Te[(size_t)N_ENT * DIM];   // transformed embeddings (current rel)
__device__ float    g_Z [(size_t)N_ENT * DIM];   // accumulator
// packed bf16x2 (k-pairs) operands, row pitch 64 words (=128 k)
__device__ unsigned g_Ah[(size_t)N_ENT * 64], g_Al[(size_t)N_ENT * 64];
__device__ unsigned g_Hh[(size_t)NB * 64],    g_Hl[(size_t)NB * 64];
__device__ unsigned g_Th[(size_t)NB * 64],    g_Tl[(size_t)NB * 64];
// packed weights: [9 mats][n=128][kp=64], mat 8 = self kernel
__device__ unsigned g_Wh[9 * 128 * 64],       g_Wl[9 * 128 * 64];

// ---------------------------------------------------------------------------
// bf16 split/pack helpers
// ---------------------------------------------------------------------------
__device__ __forceinline__ void split_pack(float x, unsigned short& h, unsigned short& l) {
    __nv_bfloat16 hb = __float2bfloat16(x);
    float hf = __bfloat162float(hb);
    __nv_bfloat16 lb = __float2bfloat16(x - hf);
    h = __bfloat16_as_ushort(hb);
    l = __bfloat16_as_ushort(lb);
}

// ---------------------------------------------------------------------------
// Pack rows: src [rows,128] f32 -> hi/lo [rows,64] bf16x2 words
// dsel: 0 = emb, 1 = head_e, 2 = tail_e
// ---------------------------------------------------------------------------
__global__ void __launch_bounds__(256) pack_rows(const float* __restrict__ src,
                                                 int dsel, int nwords) {
    int w = blockIdx.x * 256 + threadIdx.x;
    if (w >= nwords) return;
    unsigned* hi = dsel == 0 ? g_Ah : (dsel == 1 ? g_Hh : g_Th);
    unsigned* lo = dsel == 0 ? g_Al : (dsel == 1 ? g_Hl : g_Tl);
    float2 v = *reinterpret_cast<const float2*>(src + 2 * (size_t)w);
    unsigned short h0, l0, h1, l1;
    split_pack(v.x, h0, l0);
    split_pack(v.y, h1, l1);
    hi[w] = (unsigned)h0 | ((unsigned)h1 << 16);
    lo[w] = (unsigned)l0 | ((unsigned)l1 << 16);
}

// ---------------------------------------------------------------------------
// Pack weights (transpose): W [128 k,128 n] -> [n][kp] packed, per matrix.
// ---------------------------------------------------------------------------
__global__ void __launch_bounds__(256) pack_w(const float* __restrict__ src,
                                              int dst_off) {
    int mat = blockIdx.y;
    const float* W = src + (size_t)mat * 128 * 128;
    int idx = blockIdx.x * 256 + threadIdx.x;   // 0..8191
    int n  = idx & 127;
    int kp = idx >> 7;                          // 0..63
    float a = W[(2 * kp) * 128 + n];
    float b = W[(2 * kp + 1) * 128 + n];
    unsigned short h0, l0, h1, l1;
    split_pack(a, h0, l0);
    split_pack(b, h1, l1);
    int w = dst_off + mat * 8192 + n * 64 + kp;
    g_Wh[w] = (unsigned)h0 | ((unsigned)h1 << 16);
    g_Wl[w] = (unsigned)l0 | ((unsigned)l1 << 16);
}

// ---------------------------------------------------------------------------
// Zero Z
// ---------------------------------------------------------------------------
__global__ void __launch_bounds__(256) zero_Z_k() {
    const int n4 = N_ENT * DIM / 4;
    float4 z = make_float4(0.f, 0.f, 0.f, 0.f);
    for (int i = blockIdx.x * blockDim.x + threadIdx.x; i < n4;
         i += gridDim.x * blockDim.x) {
        reinterpret_cast<float4*>(g_Z)[i] = z;
    }
}

// ---------------------------------------------------------------------------
// mma + ldmatrix wrappers
// ---------------------------------------------------------------------------
__device__ __forceinline__ void mma_bf16(float* c, const unsigned* a, const unsigned* b) {
    asm volatile(
        "mma.sync.aligned.m16n8k16.row.col.f32.bf16.bf16.f32 "
        "{%0,%1,%2,%3}, {%4,%5,%6,%7}, {%8,%9}, {%0,%1,%2,%3};"
        : "+f"(c[0]), "+f"(c[1]), "+f"(c[2]), "+f"(c[3])
        : "r"(a[0]), "r"(a[1]), "r"(a[2]), "r"(a[3]), "r"(b[0]), "r"(b[1]));
}
__device__ __forceinline__ void ldm_x4(unsigned* r, unsigned saddr) {
    asm volatile("ldmatrix.sync.aligned.m8n8.x4.shared.b16 {%0,%1,%2,%3}, [%4];"
                 : "=r"(r[0]), "=r"(r[1]), "=r"(r[2]), "=r"(r[3]) : "r"(saddr));
}

// ---------------------------------------------------------------------------
// GEMM core: C[64 rows,128] = A @ W, bf16 3-product split, pre-packed inputs.
// 256 thr = 8 warps (2m x 4n), warp tile 32x32, BK=32 (16 kp), 4 k-tiles.
// EPI=0: -> g_Te.  EPI=1: out = sigmoid(C + Z[idx[row]]).
// ---------------------------------------------------------------------------
#define PITCH 20
template <int EPI>
__device__ __forceinline__ void gemm_core(int asel, int woff,
                                          const int* __restrict__ idx,
                                          float* __restrict__ out, int M) {
    __shared__ unsigned Ash[64 * PITCH], Asl[64 * PITCH];
    __shared__ unsigned Wsh[128 * PITCH], Wsl[128 * PITCH];

    const unsigned* Ah = asel == 0 ? g_Ah : (asel == 1 ? g_Hh : g_Th);
    const unsigned* Al = asel == 0 ? g_Al : (asel == 1 ? g_Hl : g_Tl);
    const unsigned* Wh = g_Wh + woff;
    const unsigned* Wl = g_Wl + woff;

    const int tid    = threadIdx.x;
    const int lane   = tid & 31;
    const int wid    = tid >> 5;
    const int warp_m = wid >> 2;          // 0..1
    const int warp_n = wid & 3;           // 0..3
    const int m0     = blockIdx.x * 64;
    const int gq     = lane >> 2;
    const int tg     = lane & 3;
    const int lane8  = lane & 7;
    const int tsel   = lane >> 3;         // 0..3 (ldmatrix tile)

    unsigned sAh = (unsigned)__cvta_generic_to_shared(Ash);
    unsigned sAl = (unsigned)__cvta_generic_to_shared(Asl);
    unsigned sWh = (unsigned)__cvta_generic_to_shared(Wsh);
    unsigned sWl = (unsigned)__cvta_generic_to_shared(Wsl);

    float acc[2][4][4];
#pragma unroll
    for (int i = 0; i < 2; i++)
#pragma unroll
        for (int j = 0; j < 4; j++)
#pragma unroll
            for (int k = 0; k < 4; k++) acc[i][j][k] = 0.f;

#pragma unroll
    for (int kt = 0; kt < 4; kt++) {
        const int K0 = kt * 16;           // kp base
        // ---- load A tile: 64 rows x 16 kp ----
        {
            int row = tid >> 2, q = tid & 3;
            int gr = m0 + row;
            uint4 vh = make_uint4(0, 0, 0, 0), vl = make_uint4(0, 0, 0, 0);
            if (gr < M) {
                size_t s = (size_t)gr * 64 + K0 + q * 4;
                vh = *reinterpret_cast<const uint4*>(Ah + s);
                vl = *reinterpret_cast<const uint4*>(Al + s);
            }
            int d = row * PITCH + q * 4;
            *reinterpret_cast<uint4*>(Ash + d) = vh;
            *reinterpret_cast<uint4*>(Asl + d) = vl;
        }
        // ---- load W tile: 128 n x 16 kp ----
#pragma unroll
        for (int i = 0; i < 2; i++) {
            int li = tid + i * 256;
            int n = li >> 2, q = li & 3;
            size_t s = (size_t)n * 64 + K0 + q * 4;
            int d = n * PITCH + q * 4;
            *reinterpret_cast<uint4*>(Wsh + d) = *reinterpret_cast<const uint4*>(Wh + s);
            *reinterpret_cast<uint4*>(Wsl + d) = *reinterpret_cast<const uint4*>(Wl + s);
        }
        __syncthreads();

#pragma unroll
        for (int ks = 0; ks < 2; ks++) {
            const int kpb = ks * 8;
            unsigned ahi[2][4], alo[2][4];
#pragma unroll
            for (int mt = 0; mt < 2; mt++) {
                int arow = warp_m * 32 + mt * 16 + (tsel & 1) * 8 + lane8;
                int akp  = kpb + (tsel >> 1) * 4;
                unsigned off = (unsigned)(arow * PITCH + akp) * 4u;
                ldm_x4(ahi[mt], sAh + off);
                ldm_x4(alo[mt], sAl + off);
            }
#pragma unroll
            for (int np = 0; np < 2; np++) {
                int brow = warp_n * 32 + np * 16 + (tsel >> 1) * 8 + lane8;
                int bkp  = kpb + (tsel & 1) * 4;
                unsigned off = (unsigned)(brow * PITCH + bkp) * 4u;
                unsigned bh[4], bl[4];
                ldm_x4(bh, sWh + off);
                ldm_x4(bl, sWl + off);
#pragma unroll
                for (int nn = 0; nn < 2; nn++)
#pragma unroll
                    for (int mt = 0; mt < 2; mt++) {
                        float* c = acc[mt][np * 2 + nn];
                        mma_bf16(c, ahi[mt], &bh[nn * 2]);
                        mma_bf16(c, alo[mt], &bh[nn * 2]);
                        mma_bf16(c, ahi[mt], &bl[nn * 2]);
                    }
            }
        }
        __syncthreads();
    }

    // epilogue
#pragma unroll
    for (int mt = 0; mt < 2; mt++) {
#pragma unroll
        for (int half = 0; half < 2; half++) {
            int gr = m0 + warp_m * 32 + mt * 16 + gq + half * 8;
            if (gr >= M) continue;
            if (EPI == 0) {
#pragma unroll
                for (int nt = 0; nt < 4; nt++) {
                    int col = warp_n * 32 + nt * 8 + 2 * tg;
                    float2 v = make_float2(acc[mt][nt][half * 2 + 0],
                                           acc[mt][nt][half * 2 + 1]);
                    *reinterpret_cast<float2*>(&g_Te[(size_t)gr * 128 + col]) = v;
                }
            } else {
                int node = __ldg(&idx[gr]);
#pragma unroll
                for (int nt = 0; nt < 4; nt++) {
                    int col = warp_n * 32 + nt * 8 + 2 * tg;
                    float2 z = *reinterpret_cast<const float2*>(&g_Z[(size_t)node * 128 + col]);
                    float2 o;
                    o.x = 1.f / (1.f + expf(-(acc[mt][nt][half * 2 + 0] + z.x)));
                    o.y = 1.f / (1.f + expf(-(acc[mt][nt][half * 2 + 1] + z.y)));
                    *reinterpret_cast<float2*>(&out[(size_t)gr * 128 + col]) = o;
                }
            }
        }
    }
}

__global__ void __launch_bounds__(256, 3) gemm_te_tc(int woff, int M) {
    gemm_core<0>(0, woff, nullptr, nullptr, M);
}
__global__ void __launch_bounds__(256, 3) out_tc(int asel, int woff,
                                                 const int* __restrict__ idx,
                                                 float* __restrict__ out, int M) {
    gemm_core<1>(asel, woff, idx, out, M);
}

// ---------------------------------------------------------------------------
// Scatter: Z[src] += val * Te[dst]  (one edge per warp, red.v4 per lane)
// ---------------------------------------------------------------------------
__global__ void __launch_bounds__(256) scatter_k(const int*   __restrict__ src,
                                                 const int*   __restrict__ dst,
                                                 const float* __restrict__ val) {
    int w    = (blockIdx.x * 256 + threadIdx.x) >> 5;
    int lane = threadIdx.x & 31;
    if (w >= NE) return;
    int   s = __ldg(&src[w]);
    int   d = __ldg(&dst[w]);
    float v = __ldg(&val[w]);
    float4 t = *reinterpret_cast<const float4*>(&g_Te[(size_t)d * 128 + lane * 4]);
    float* zp = &g_Z[(size_t)s * 128 + lane * 4];
    asm volatile("red.global.add.v4.f32 [%0], {%1, %2, %3, %4};"
                 :: "l"(zp), "f"(t.x * v), "f"(t.y * v), "f"(t.z * v), "f"(t.w * v)
                 : "memory");
}

// ---------------------------------------------------------------------------
// Launch
// ---------------------------------------------------------------------------
extern "C" void kernel_launch(void* const* d_in, const int* in_sizes, int n_in,
                              void* d_out, int out_size) {
    const float* emb      = (const float*)d_in[0];
    const float* head_e   = (const float*)d_in[1];
    const float* tail_e   = (const float*)d_in[2];
    const float* relk     = (const float*)d_in[3];  // [R,128,128]
    const float* selfk    = (const float*)d_in[4];  // [128,128]
    const float* edge_val = (const float*)d_in[5];  // [R,E]
    const int*   head_idx = (const int*)d_in[6];
    const int*   tail_idx = (const int*)d_in[7];
    const int*   edge_src = (const int*)d_in[8];    // [R,E]
    const int*   edge_dst = (const int*)d_in[9];    // [R,E]
    float*       out      = (float*)d_out;          // [2, B, 128], head first

    pack_rows<<<(N_ENT * 64 + 255) / 256, 256>>>(emb,    0, N_ENT * 64);
    pack_rows<<<(NB * 64 + 255) / 256, 256>>>(head_e, 1, NB * 64);
    pack_rows<<<(NB * 64 + 255) / 256, 256>>>(tail_e, 2, NB * 64);
    pack_w<<<dim3(32, NR), 256>>>(relk, 0);
    pack_w<<<dim3(32, 1), 256>>>(selfk, NR * 8192);

    zero_Z_k<<<2048, 256>>>();

    const int gemm_blocks = (N_ENT + 63) / 64;        // 1563
    const int scat_blocks = (NE * 32 + 255) / 256;    // 25000
    for (int r = 0; r < NR; r++) {
        gemm_te_tc<<<gemm_blocks, 256>>>(r * 8192, N_ENT);
        scatter_k<<<scat_blocks, 256>>>(edge_src + (size_t)r * NE,
                                        edge_dst + (size_t)r * NE,
                                        edge_val + (size_t)r * NE);
    }

    const int out_blocks = (NB + 63) / 64;            // 782
    out_tc<<<out_blocks, 256>>>(1, NR * 8192, head_idx, out, NB);
    out_tc<<<out_blocks, 256>>>(2, NR * 8192, tail_idx, out + (size_t)NB * 128, NB);
}